// round 3
// baseline (speedup 1.0000x reference)
#include <cuda_runtime.h>
#include <stdint.h>

// TernaryLinear: out = (x @ ternary(W).T + bias) * scale
//   x: [8192, 4096] fp32, W: [4096, 4096] fp32, scale/bias: [4096] fp32
//   ternary(W) = 0 where |W| < 0.1f else sign(W)
//
// W ~ U(-0.1, 0.1): fp32-grid analysis shows essentially every entry has
// |w| < 0.1 exactly -> ternary matrix has ~Poisson(2) nonzeros. One streaming
// pass compresses W into a flat (o,i,sign) list; the output kernel is then an
// exact fp32 gather + epilogue bound by the 128 MB output write.
// Counter reset is done device-side by the LAST block of tl_compress via an
// atomicInc-wrap arrival counter, so all __device__ state returns to its
// initial value after every launch (graph-replay deterministic, no memset
// node, no extra kernel).
// If the list ever overflows CAP (impossible for this distribution), the
// output kernel falls back to an exact dense ternary dot read from W.

#define IN_DIM  4096
#define OUT_DIM 4096
#define ROWS_PER_BLOCK 8
#define CAP 4096

// |w| >= 0.1f (or NaN)  <=>  (bits & 0x7fffffff) >= bits(0.1f)
#define ABS_THRESH_BITS 0x3dcccccdu

__device__ int      g_n;         // entry counter (always 0 between launches)
__device__ unsigned g_done;      // arrival counter (wraps back to 0)
__device__ int      g_total;     // published entry count for the output kernel
__device__ int      g_entries[(size_t)OUT_DIM * IN_DIM];  // worst-case 64 MB

// ---------------------------------------------------------------------------
// Kernel A: ternarize + compress. One streaming pass over 64 MB (int4 loads),
// integer bitwise threshold. entry = (o<<13) | (i<<1) | negbit.
// Last-arriving block publishes g_total and resets g_n to 0.
// ---------------------------------------------------------------------------
__global__ void __launch_bounds__(256) tl_compress(const int* __restrict__ w) {
    const int total4 = (OUT_DIM * IN_DIM) / 4;
    int stride = gridDim.x * blockDim.x;
    for (int j = blockIdx.x * blockDim.x + threadIdx.x; j < total4; j += stride) {
        int4 v = reinterpret_cast<const int4*>(w)[j];
        int vals[4] = {v.x, v.y, v.z, v.w};
        int base = j * 4;
#pragma unroll
        for (int k = 0; k < 4; k++) {
            unsigned bits = (unsigned)vals[k];
            if ((bits & 0x7fffffffu) >= ABS_THRESH_BITS) {
                int lin = base + k;
                int o = lin >> 12;              // W row = output channel
                int i = lin & (IN_DIM - 1);     // input index
                int pos = atomicAdd(&g_n, 1);
                g_entries[pos] = (o << 13) | (i << 1) | (int)(bits >> 31);
            }
        }
    }

    // Arrival: last block snapshots the count and resets it for next replay.
    __syncthreads();
    if (threadIdx.x == 0) {
        __threadfence();
        unsigned ticket = atomicInc(&g_done, gridDim.x - 1);
        if (ticket == gridDim.x - 1) {          // I am the last block
            g_total = g_n;                      // atomic-coherent read
            g_n = 0;                            // state restored for replay
        }
    }
}

// ---------------------------------------------------------------------------
// Kernel B: output. Each thread owns 4 consecutive o (float4 epilogue+store),
// ROWS_PER_BLOCK rows per block. Entry list broadcast via shared memory.
// ---------------------------------------------------------------------------
__global__ void __launch_bounds__(256) tl_output(
        const float* __restrict__ x,
        const float* __restrict__ w,
        const float* __restrict__ scale,
        const float* __restrict__ bias,
        float* __restrict__ out, int N) {
    __shared__ int se[CAP];
    __shared__ int s_ne;

    int tid = threadIdx.x;
    if (tid == 0) s_ne = g_total;
    __syncthreads();
    int ne = s_ne;

    int o4 = (blockIdx.x * 256 + tid) * 4;      // first of my 4 outputs
    int n0 = blockIdx.y * ROWS_PER_BLOCK;

    float4 sc = *reinterpret_cast<const float4*>(scale + o4);
    float4 bi = *reinterpret_cast<const float4*>(bias + o4);

    if (ne <= CAP) {
        // ---- sparse path (always taken in practice; ne ~ 2) ----
        for (int i = tid; i < ne; i += 256) se[i] = g_entries[i];
        __syncthreads();

#pragma unroll
        for (int r = 0; r < ROWS_PER_BLOCK; r++) {
            int n = n0 + r;
            if (n >= N) break;
            const float* xr = x + (size_t)n * IN_DIM;
            float a0 = 0.f, a1 = 0.f, a2 = 0.f, a3 = 0.f;
            for (int e = 0; e < ne; e++) {
                int v  = se[e];
                unsigned d = (unsigned)((v >> 13) - o4);
                if (d < 4u) {
                    float xv = __ldg(&xr[(v >> 1) & (IN_DIM - 1)]);
                    float sv = (v & 1) ? -xv : xv;
                    if      (d == 0u) a0 += sv;
                    else if (d == 1u) a1 += sv;
                    else if (d == 2u) a2 += sv;
                    else              a3 += sv;
                }
            }
            float4 res;
            res.x = (a0 + bi.x) * sc.x;
            res.y = (a1 + bi.y) * sc.y;
            res.z = (a2 + bi.z) * sc.z;
            res.w = (a3 + bi.w) * sc.w;
            *reinterpret_cast<float4*>(out + (size_t)n * OUT_DIM + o4) = res;
        }
    } else {
        // ---- dense fallback (correctness safety net; never taken here) ----
#pragma unroll 1
        for (int r = 0; r < ROWS_PER_BLOCK; r++) {
            int n = n0 + r;
            if (n >= N) break;
            const float* xr = x + (size_t)n * IN_DIM;
            float a[4] = {0.f, 0.f, 0.f, 0.f};
            for (int k = 0; k < IN_DIM; k++) {
                float xv = __ldg(&xr[k]);
#pragma unroll
                for (int q = 0; q < 4; q++) {
                    unsigned bits = __float_as_uint(
                        __ldg(&w[(size_t)(o4 + q) * IN_DIM + k]));
                    if ((bits & 0x7fffffffu) >= ABS_THRESH_BITS)
                        a[q] += (bits >> 31) ? -xv : xv;
                }
            }
            float4 res;
            res.x = (a[0] + bi.x) * sc.x;
            res.y = (a[1] + bi.y) * sc.y;
            res.z = (a[2] + bi.z) * sc.z;
            res.w = (a[3] + bi.w) * sc.w;
            *reinterpret_cast<float4*>(out + (size_t)n * OUT_DIM + o4) = res;
        }
    }
}

// ---------------------------------------------------------------------------
extern "C" void kernel_launch(void* const* d_in, const int* in_sizes, int n_in,
                              void* d_out, int out_size) {
    const float* x     = (const float*)d_in[0];
    const float* w     = (const float*)d_in[1];
    const float* scale = (const float*)d_in[2];
    const float* bias  = (const float*)d_in[3];
    float* out = (float*)d_out;

    int N = in_sizes[0] / IN_DIM;   // 8192

    tl_compress<<<2368, 256>>>((const int*)w);

    dim3 grid(OUT_DIM / (256 * 4), (N + ROWS_PER_BLOCK - 1) / ROWS_PER_BLOCK);
    tl_output<<<grid, 256>>>(x, w, scale, bias, out, N);
}